// round 11
// baseline (speedup 1.0000x reference)
#include <cuda_runtime.h>
#include <cuda_fp16.h>
#include <cstdint>
#include <math.h>

// Problem constants
#define B_   2
#define S_   2048
#define M_   (B_*S_)      // 4096 rows
#define DIM_ 1024
#define DFF_ 4096
#define NH_  16
#define HD_  64
#define EPSV 1e-6f

typedef __half f16;

// ---------------- scratch (device globals; no allocations allowed) ----------
__device__ __align__(16) f16   g_ln  [M_*DIM_];
__device__ __align__(16) f16   g_qkv [(size_t)M_*3*DIM_];
__device__ __align__(16) f16   g_at  [M_*DIM_];
__device__ __align__(16) float g_x1  [M_*DIM_];
__device__ __align__(16) f16   g_ff  [(size_t)M_*DFF_];
// fp16 weights in ORIGINAL [K][N] layout (no transpose; B uses ldmatrix.trans)
__device__ __align__(16) f16   g_wqkv[(size_t)DIM_*3*DIM_];   // [1024][3072] (q|k|v)
__device__ __align__(16) f16   g_wo  [DIM_*DIM_];             // [1024][1024]
__device__ __align__(16) f16   g_up  [(size_t)DIM_*DFF_];     // [1024][4096]
__device__ __align__(16) f16   g_dn  [(size_t)DFF_*DIM_];     // [4096][1024]

// ---------------- PTX helpers ------------------------------------------------
__device__ __forceinline__ uint32_t smem_u32(const void* p) {
    uint32_t a;
    asm("{ .reg .u64 t; cvta.to.shared.u64 t, %1; cvt.u32.u64 %0, t; }" : "=r"(a) : "l"(p));
    return a;
}
__device__ __forceinline__ void cp_async16(uint32_t saddr, const void* gaddr) {
    asm volatile("cp.async.cg.shared.global [%0], [%1], 16;" :: "r"(saddr), "l"(gaddr) : "memory");
}
__device__ __forceinline__ void cp_commit() {
    asm volatile("cp.async.commit_group;" ::: "memory");
}
template<int N>
__device__ __forceinline__ void cp_wait() {
    asm volatile("cp.async.wait_group %0;" :: "n"(N) : "memory");
}
__device__ __forceinline__ void ldm_x4(uint32_t& r0, uint32_t& r1, uint32_t& r2, uint32_t& r3,
                                       uint32_t addr) {
    asm volatile("ldmatrix.sync.aligned.m8n8.x4.shared.b16 {%0,%1,%2,%3}, [%4];"
                 : "=r"(r0), "=r"(r1), "=r"(r2), "=r"(r3) : "r"(addr));
}
__device__ __forceinline__ void ldm_x4t(uint32_t& r0, uint32_t& r1, uint32_t& r2, uint32_t& r3,
                                        uint32_t addr) {
    asm volatile("ldmatrix.sync.aligned.m8n8.x4.trans.shared.b16 {%0,%1,%2,%3}, [%4];"
                 : "=r"(r0), "=r"(r1), "=r"(r2), "=r"(r3) : "r"(addr));
}
__device__ __forceinline__ void mma_f16(float* c, const uint32_t* a, const uint32_t* b) {
    asm volatile("mma.sync.aligned.m16n8k16.row.col.f32.f16.f16.f32 "
                 "{%0,%1,%2,%3}, {%4,%5,%6,%7}, {%8,%9}, {%0,%1,%2,%3};"
                 : "+f"(c[0]), "+f"(c[1]), "+f"(c[2]), "+f"(c[3])
                 : "r"(a[0]), "r"(a[1]), "r"(a[2]), "r"(a[3]), "r"(b[0]), "r"(b[1]));
}
// packs {lo=a, hi=b}
__device__ __forceinline__ uint32_t pack_f16(float a, float b) {
    uint32_t r;
    asm("cvt.rn.f16x2.f32 %0, %1, %2;" : "=r"(r) : "f"(b), "f"(a));
    return r;
}

// ---------------- one-shot fp32 -> fp16 weight convert (NO transpose) --------
// units of 4 elems; segments: wq|wk|wv (interleave into [1024][3072]), wo, up, dn
__global__ __launch_bounds__(256) void conv_all(
    const float* __restrict__ wq, const float* __restrict__ wk,
    const float* __restrict__ wv, const float* __restrict__ wo,
    const float* __restrict__ up, const float* __restrict__ dn,
    f16* __restrict__ dqkv, f16* __restrict__ dwo,
    f16* __restrict__ dup, f16* __restrict__ ddn)
{
    size_t t = (size_t)blockIdx.x * 256 + threadIdx.x;   // one float4 per thread
    const float* src;
    f16* dst;
    if (t < 786432) {                        // 3 x 262144 units (wq, wk, wv)
        int seg = (int)(t >> 18);
        size_t e = (t & 262143) * 4;
        int k = (int)(e >> 10), n = (int)(e & 1023);
        src = (seg == 0 ? wq : seg == 1 ? wk : wv) + e;
        dst = dqkv + (size_t)k * 3072 + seg * 1024 + n;
    } else if (t < 1048576) {                // wo: 262144 units
        size_t e = (t - 786432) * 4;
        src = wo + e; dst = dwo + e;
    } else if (t < 2097152) {                // up: 1M units
        size_t e = (t - 1048576) * 4;
        src = up + e; dst = dup + e;
    } else {                                 // dn: 1M units
        size_t e = (t - 2097152) * 4;
        src = dn + e; dst = ddn + e;
    }
    float4 v = *(const float4*)src;
    __half2 h0 = __floats2half2_rn(v.x, v.y);
    __half2 h1 = __floats2half2_rn(v.z, v.w);
    uint2 o;
    o.x = *(uint32_t*)&h0;
    o.y = *(uint32_t*)&h1;
    *(uint2*)dst = o;
}

// ---------------- LayerNorm -> fp16 ------------------------------------------
__global__ __launch_bounds__(256) void ln_kernel(
    const float* __restrict__ x, const float* __restrict__ alpha,
    const float* __restrict__ beta, f16* __restrict__ outp)
{
    int row = blockIdx.x;
    const float* xr = x + (size_t)row * DIM_;
    int tid = threadIdx.x;

    float v[4];
    float s = 0.f, s2 = 0.f;
#pragma unroll
    for (int j = 0; j < 4; j++) {
        v[j] = xr[tid + j * 256];
        s += v[j]; s2 += v[j] * v[j];
    }
#pragma unroll
    for (int o = 16; o > 0; o >>= 1) {
        s  += __shfl_xor_sync(0xffffffffu, s,  o);
        s2 += __shfl_xor_sync(0xffffffffu, s2, o);
    }
    __shared__ float rs[8], rs2[8];
    int wid = tid >> 5, lid = tid & 31;
    if (lid == 0) { rs[wid] = s; rs2[wid] = s2; }
    __syncthreads();
    s = 0.f; s2 = 0.f;
#pragma unroll
    for (int i = 0; i < 8; i++) { s += rs[i]; s2 += rs2[i]; }

    float mu  = s * (1.0f / DIM_);
    float var = (s2 - (float)DIM_ * mu * mu) * (1.0f / (DIM_ - 1));
    float inv = 1.0f / (sqrtf(fmaxf(var, 0.f)) + EPSV);
#pragma unroll
    for (int j = 0; j < 4; j++) {
        int c = tid + j * 256;
        float y = alpha[c] * (v[j] - mu) * inv + beta[c];
        outp[(size_t)row * DIM_ + c] = __float2half_rn(y);
    }
}

// ---------------- HMMA fp16 GEMM: C[M,N] = A[M,K] @ W[K,N] -------------------
// A row-major [M][K]; W row-major [K][N] (B frags via ldmatrix.trans).
// CTA tile 128x256, 8 warps (64x64 each), K-chunk 64, 2-stage cp.async.
#define APITCH 144
#define ABYTES (128 * APITCH)                 // 18432
#define BPITCH 528
#define BBYTES (64 * BPITCH)                  // 33792
#define STAGE_BYTES (ABYTES + BBYTES)         // 52224
#define GEMM_SMEM   (2 * STAGE_BYTES + 256)

__global__ __launch_bounds__(256, 1)
void gemm_f16(const f16* __restrict__ A, const f16* __restrict__ Bw,
              const float* __restrict__ bias, const float* __restrict__ resid,
              float* __restrict__ Cf, f16* __restrict__ Ch,
              int M, int N, int K, int relu)
{
    extern __shared__ char dsm[];
    char* sb = (char*)(((uintptr_t)dsm + 127) & ~(uintptr_t)127);
    uint32_t sb32 = smem_u32(sb);

    int tid = threadIdx.x, wid = tid >> 5, lane = tid & 31;
    int rowBase = blockIdx.y * 128, colBase = blockIdx.x * 256;
    int wm = wid & 1, wn = wid >> 1;     // warp tile: rows wm*64, cols wn*64

    float acc[4][8][4];
#pragma unroll
    for (int i = 0; i < 4; i++)
#pragma unroll
        for (int j = 0; j < 8; j++)
#pragma unroll
            for (int q = 0; q < 4; q++) acc[i][j][q] = 0.f;

    // A x4 frag: rows lane&15, k-halves by lane>>4
    uint32_t aOff = (uint32_t)(wm * 64 + (lane & 15)) * APITCH + (uint32_t)((lane >> 4) * 16);
    // B x4t frag (proven attention-PV pattern): k rows lane&15 (within ks*16),
    // n-halves by (lane>>4)&1; warp n-window = wn*64 cols (128 bytes)
    uint32_t bLane = ABYTES + (uint32_t)(lane & 15) * BPITCH
                   + (uint32_t)(wn * 128) + (uint32_t)(((lane >> 4) & 1) * 16);

    int NC = K >> 6;

    // stage loader: A 128 rows x 8 chunks + B 64 rows x 32 chunks = 3072
    auto load_stage = [&](int ch, int s) {
        int k0 = ch << 6;
        uint32_t stage = sb32 + s * STAGE_BYTES;
#pragma unroll
        for (int it = 0; it < 12; it++) {
            int idx = it * 256 + tid;
            if (idx < 1024) {
                int r = idx >> 3, c = idx & 7;
                cp_async16(stage + r * APITCH + c * 16,
                           A + (size_t)(rowBase + r) * K + k0 + c * 8);
            } else {
                int j = idx - 1024;
                int r = j >> 5, c = j & 31;
                cp_async16(stage + ABYTES + r * BPITCH + c * 16,
                           Bw + (size_t)(k0 + r) * N + colBase + c * 8);
            }
        }
        cp_commit();
    };

    load_stage(0, 0);

    for (int ch = 0; ch < NC; ch++) {
        int s = ch & 1;
        if (ch + 1 < NC) { load_stage(ch + 1, s ^ 1); cp_wait<1>(); }
        else             { cp_wait<0>(); }
        __syncthreads();

        uint32_t stage = sb32 + s * STAGE_BYTES;
        uint32_t aBase = stage + aOff;
        uint32_t bBase = stage + bLane;

#pragma unroll
        for (int ks = 0; ks < 4; ks++) {
            uint32_t aF[4][4], bF[4][4];
#pragma unroll
            for (int mt = 0; mt < 4; mt++)
                ldm_x4(aF[mt][0], aF[mt][1], aF[mt][2], aF[mt][3],
                       aBase + mt * (16 * APITCH) + ks * 32);
#pragma unroll
            for (int ntp = 0; ntp < 4; ntp++)
                ldm_x4t(bF[ntp][0], bF[ntp][1], bF[ntp][2], bF[ntp][3],
                        bBase + (uint32_t)(ks * 16) * BPITCH + ntp * 32);
#pragma unroll
            for (int mt = 0; mt < 4; mt++)
#pragma unroll
                for (int ntp = 0; ntp < 4; ntp++) {
                    mma_f16(acc[mt][2*ntp],   aF[mt], bF[ntp] + 0);
                    mma_f16(acc[mt][2*ntp+1], aF[mt], bF[ntp] + 2);
                }
        }
        __syncthreads();
    }

    // epilogue
    int tr = lane >> 2;
    int tc = (lane & 3) * 2;
#pragma unroll
    for (int mt = 0; mt < 4; mt++) {
#pragma unroll
        for (int half = 0; half < 2; half++) {
            int r = rowBase + wm * 64 + mt * 16 + tr + half * 8;
#pragma unroll
            for (int nt = 0; nt < 8; nt++) {
                int cg = colBase + wn * 64 + nt * 8 + tc;
                size_t off = (size_t)r * N + cg;
                float v0 = acc[mt][nt][half * 2 + 0];
                float v1 = acc[mt][nt][half * 2 + 1];
                if (bias)  { v0 += bias[cg]; v1 += bias[cg + 1]; }
                if (relu)  { v0 = fmaxf(v0, 0.f); v1 = fmaxf(v1, 0.f); }
                if (resid) { v0 += resid[off]; v1 += resid[off + 1]; }
                if (Cf) *(float2*)&Cf[off] = make_float2(v0, v1);
                if (Ch) *(uint32_t*)&Ch[off] = pack_f16(v0, v1);
            }
        }
    }
}

// ---------------- HMMA fp16 flash attention ----------------------------------
// QKV layout [M][3072]: q = h*64+d, k = +1024, v = +2048.
// 256 threads (8 warps), 128 q-rows/block, 64-key chunks, double-buffered K/V.
#define AT_PITCH 144
#define AT_PLANE (64 * AT_PITCH)          // 9216
#define Q_BYTES  (128 * AT_PITCH)         // 18432
#define KV_STAGE (2 * AT_PLANE)           // K + V per stage
#define ATTN_SMEM (Q_BYTES + 2 * KV_STAGE + 256)

__global__ __launch_bounds__(256) void attn_mma(
    const f16* __restrict__ QKV, f16* __restrict__ O)
{
    extern __shared__ char sm_[];
    char* base = (char*)(((uintptr_t)sm_ + 127) & ~(uintptr_t)127);
    uint32_t sb = smem_u32(base);
    uint32_t qS = sb;
    uint32_t kvS = sb + Q_BYTES;          // stage s: K at +s*KV_STAGE, V at +AT_PLANE

    int tid = threadIdx.x, warp = tid >> 5, lane = tid & 31;
    int qt = blockIdx.x, bh = blockIdx.y;
    int b = bh >> 4, h = bh & 15;
    int qrow0 = b * S_ + qt * 128;

    // ---- load Q tile (128 rows x 128B) ----
#pragma unroll
    for (int it = 0; it < 4; it++) {
        int idx = it * 256 + tid;
        int r = idx >> 3, c = idx & 7;
        cp_async16(qS + r * AT_PITCH + c * 16,
                   QKV + (size_t)(qrow0 + r) * (3 * DIM_) + h * HD_ + c * 8);
    }
    cp_commit();

    // ---- K/V chunk loader (64 rows each) ----
    auto load_kv = [&](int kt, int s) {
        uint32_t st = kvS + s * KV_STAGE;
        size_t rowg = (size_t)(b * S_ + kt * 64) * (3 * DIM_) + DIM_ + h * HD_;
#pragma unroll
        for (int it = 0; it < 2; it++) {
            int idx = it * 256 + tid;
            int r = idx >> 3, c = idx & 7;
            size_t g = rowg + (size_t)r * (3 * DIM_) + c * 8;
            cp_async16(st + r * AT_PITCH + c * 16, QKV + g);           // K
            cp_async16(st + AT_PLANE + r * AT_PITCH + c * 16, QKV + g + DIM_); // V
        }
        cp_commit();
    };

    load_kv(0, 0);
    cp_wait<1>();     // Q done (group 0 retired when <=1 pending)
    __syncthreads();

    // ---- preload Q fragments ----
    uint32_t qf[4][4];
    {
        uint32_t aAddr = qS + (uint32_t)(warp * 16 + (lane & 15)) * AT_PITCH
                       + ((lane >> 4) * 16);
#pragma unroll
        for (int ks = 0; ks < 4; ks++)
            ldm_x4(qf[ks][0], qf[ks][1], qf[ks][2], qf[ks][3], aAddr + ks * 32);
    }

    float oacc[8][4];
#pragma unroll
    for (int i = 0; i < 8; i++)
#pragma unroll
        for (int j = 0; j < 4; j++) oacc[i][j] = 0.f;
    float m0 = -1e30f, m1 = -1e30f, l0 = 0.f, l1 = 0.f;

    uint32_t bAddrBase = (uint32_t)(((lane >> 4) & 1) * 8 + (lane & 7)) * AT_PITCH
                       + ((lane >> 3) & 1) * 16;

    const int NT = S_ / 64;
    for (int kt = 0; kt < NT; kt++) {
        int s = kt & 1;
        if (kt + 1 < NT) { load_kv(kt + 1, s ^ 1); cp_wait<1>(); }
        else             { cp_wait<0>(); }
        __syncthreads();

        uint32_t kS = kvS + s * KV_STAGE;
        uint32_t vS = kS + AT_PLANE;

        // ---- S = Q K^T ----
        float sacc[8][4];
#pragma unroll
        for (int i = 0; i < 8; i++)
#pragma unroll
            for (int j = 0; j < 4; j++) sacc[i][j] = 0.f;

#pragma unroll
        for (int ks = 0; ks < 4; ks++) {
#pragma unroll
            for (int ntp = 0; ntp < 4; ntp++) {
                uint32_t addr = kS + bAddrBase + (uint32_t)(ntp * 16) * AT_PITCH + ks * 32;
                uint32_t b4[4];
                ldm_x4(b4[0], b4[1], b4[2], b4[3], addr);
                mma_f16(sacc[2*ntp],   qf[ks], b4 + 0);
                mma_f16(sacc[2*ntp+1], qf[ks], b4 + 2);
            }
        }

        // ---- online softmax ----
        float mx0 = -1e30f, mx1 = -1e30f;
#pragma unroll
        for (int nt = 0; nt < 8; nt++) {
#pragma unroll
            for (int j = 0; j < 4; j++) sacc[nt][j] *= 0.125f;
            mx0 = fmaxf(mx0, fmaxf(sacc[nt][0], sacc[nt][1]));
            mx1 = fmaxf(mx1, fmaxf(sacc[nt][2], sacc[nt][3]));
        }
        mx0 = fmaxf(mx0, __shfl_xor_sync(0xffffffffu, mx0, 1));
        mx0 = fmaxf(mx0, __shfl_xor_sync(0xffffffffu, mx0, 2));
        mx1 = fmaxf(mx1, __shfl_xor_sync(0xffffffffu, mx1, 1));
        mx1 = fmaxf(mx1, __shfl_xor_sync(0xffffffffu, mx1, 2));

        float nm0 = fmaxf(m0, mx0), nm1 = fmaxf(m1, mx1);
        float corr0 = __expf(m0 - nm0), corr1 = __expf(m1 - nm1);
        float rs0 = 0.f, rs1 = 0.f;
#pragma unroll
        for (int nt = 0; nt < 8; nt++) {
            sacc[nt][0] = __expf(sacc[nt][0] - nm0);
            sacc[nt][1] = __expf(sacc[nt][1] - nm0);
            sacc[nt][2] = __expf(sacc[nt][2] - nm1);
            sacc[nt][3] = __expf(sacc[nt][3] - nm1);
            rs0 += sacc[nt][0] + sacc[nt][1];
            rs1 += sacc[nt][2] + sacc[nt][3];
        }
        rs0 += __shfl_xor_sync(0xffffffffu, rs0, 1);
        rs0 += __shfl_xor_sync(0xffffffffu, rs0, 2);
        rs1 += __shfl_xor_sync(0xffffffffu, rs1, 1);
        rs1 += __shfl_xor_sync(0xffffffffu, rs1, 2);
        l0 = l0 * corr0 + rs0;  m0 = nm0;
        l1 = l1 * corr1 + rs1;  m1 = nm1;
#pragma unroll
        for (int nt = 0; nt < 8; nt++) {
            oacc[nt][0] *= corr0; oacc[nt][1] *= corr0;
            oacc[nt][2] *= corr1; oacc[nt][3] *= corr1;
        }

        // ---- O += P V ----
#pragma unroll
        for (int ks = 0; ks < 4; ks++) {
            uint32_t aP[4];
            float* se = sacc[2*ks];
            float* so = sacc[2*ks + 1];
            aP[0] = pack_f16(se[0], se[1]);
            aP[1] = pack_f16(se[2], se[3]);
            aP[2] = pack_f16(so[0], so[1]);
            aP[3] = pack_f16(so[2], so[3]);
#pragma unroll
            for (int ntp = 0; ntp < 4; ntp++) {
                uint32_t addr = vS + (uint32_t)(ks * 16 + (lane & 15)) * AT_PITCH
                              + (uint32_t)(ntp * 2 + ((lane >> 4) & 1)) * 16;
                uint32_t v4[4];
                ldm_x4t(v4[0], v4[1], v4[2], v4[3], addr);
                mma_f16(oacc[2*ntp],   aP, v4 + 0);
                mma_f16(oacc[2*ntp+1], aP, v4 + 2);
            }
        }
        __syncthreads();
    }

    // ---- normalize + write out ----
    float inv0 = 1.f / l0, inv1 = 1.f / l1;
    int r0g = qrow0 + warp * 16 + (lane >> 2);
    int cbase = h * HD_ + (lane & 3) * 2;
#pragma unroll
    for (int nt = 0; nt < 8; nt++) {
        float v0 = oacc[nt][0] * inv0, v1 = oacc[nt][1] * inv0;
        float v2 = oacc[nt][2] * inv1, v3 = oacc[nt][3] * inv1;
        size_t off0 = (size_t)r0g * DIM_ + cbase + nt * 8;
        size_t off1 = off0 + (size_t)8 * DIM_;
        *(uint32_t*)&O[off0] = pack_f16(v0, v1);
        *(uint32_t*)&O[off1] = pack_f16(v2, v3);
    }
}

// ---------------- launcher ---------------------------------------------------
extern "C" void kernel_launch(void* const* d_in, const int* in_sizes, int n_in,
                              void* d_out, int out_size)
{
    const float* x      = (const float*)d_in[0];
    const float* wq     = (const float*)d_in[2];
    const float* wk     = (const float*)d_in[3];
    const float* wv     = (const float*)d_in[4];
    const float* wo     = (const float*)d_in[5];
    const float* w_up   = (const float*)d_in[6];
    const float* b_up   = (const float*)d_in[7];
    const float* w_down = (const float*)d_in[8];
    const float* b_down = (const float*)d_in[9];
    const float* ln1_a  = (const float*)d_in[10];
    const float* ln1_b  = (const float*)d_in[11];
    const float* ln2_a  = (const float*)d_in[12];
    const float* ln2_b  = (const float*)d_in[13];
    float* out = (float*)d_out;

    f16 *lnp, *qkv, *at, *ff, *wqkvC, *woC, *upC, *dnC;
    float *px1;
    cudaGetSymbolAddress((void**)&lnp,   g_ln);
    cudaGetSymbolAddress((void**)&qkv,   g_qkv);
    cudaGetSymbolAddress((void**)&at,    g_at);
    cudaGetSymbolAddress((void**)&ff,    g_ff);
    cudaGetSymbolAddress((void**)&wqkvC, g_wqkv);
    cudaGetSymbolAddress((void**)&woC,   g_wo);
    cudaGetSymbolAddress((void**)&upC,   g_up);
    cudaGetSymbolAddress((void**)&dnC,   g_dn);
    cudaGetSymbolAddress((void**)&px1,   g_x1);

    cudaFuncSetAttribute(gemm_f16, cudaFuncAttributeMaxDynamicSharedMemorySize, GEMM_SMEM);
    cudaFuncSetAttribute(attn_mma, cudaFuncAttributeMaxDynamicSharedMemorySize, ATTN_SMEM);

    // one-shot weight convert (no transpose): 12M elems / 4 per thread
    conv_all<<<12288, 256>>>(wq, wk, wv, wo, w_up, w_down, wqkvC, woC, upC, dnC);

    dim3 blk(256);
    dim3 gD(DIM_/256, M_/128);      // N=1024
    dim3 gQKV(3*DIM_/256, M_/128);  // N=3072
    dim3 gF(DFF_/256, M_/128);      // N=4096

    // h = LN1(x)
    ln_kernel<<<M_, blk>>>(x, ln1_a, ln1_b, lnp);
    // fused QKV projection -> fp16 [M][3072]
    gemm_f16<<<gQKV, blk, GEMM_SMEM>>>(lnp, wqkvC, nullptr, nullptr,
                                       nullptr, qkv, M_, 3*DIM_, DIM_, 0);
    // flash attention -> fp16
    attn_mma<<<dim3(S_/128, B_*NH_), blk, ATTN_SMEM>>>(qkv, at);
    // x1 = x + attn @ wo
    gemm_f16<<<gD, blk, GEMM_SMEM>>>(at, woC, nullptr, x,
                                     px1, nullptr, M_, DIM_, DIM_, 0);
    // h = LN2(x1)
    ln_kernel<<<M_, blk>>>(px1, ln2_a, ln2_b, lnp);
    // ff = relu(h @ w_up + b_up) -> fp16
    gemm_f16<<<gF, blk, GEMM_SMEM>>>(lnp, upC, b_up, nullptr,
                                     nullptr, ff, M_, DFF_, DIM_, 1);
    // out = x1 + ff @ w_down + b_down
    gemm_f16<<<gD, blk, GEMM_SMEM>>>(ff, dnC, b_down, px1,
                                     out, nullptr, M_, DIM_, DFF_, 0);
}